// round 4
// baseline (speedup 1.0000x reference)
#include <cuda_runtime.h>
#include <math.h>
#include <stdint.h>

// Problem constants
#define Bc   2
#define Mc   2048
#define Dc   1024
#define Hc   16
#define DHc  64
#define FFc  2624
#define ROWS (Bc * Mc)      // 4096
#define QKVN (3 * Dc)       // 3072
#define WIN  (2 * FFc)      // 5248

// ---------------- scratch (device globals; no cudaMalloc allowed) ----------------
__device__ __align__(16) float g_xn  [ROWS * Dc];
__device__ __align__(16) float g_qkv [ROWS * QKVN];
__device__ __align__(16) float g_attn[ROWS * Dc];
__device__ __align__(16) float g_x1  [ROWS * Dc];
__device__ __align__(16) float g_h   [ROWS * Dc];
__device__ __align__(16) float g_g   [(size_t)ROWS * WIN];
__device__ __align__(16) float g_act [(size_t)ROWS * FFc];

// ---------------- tf32 helpers ----------------
__device__ __forceinline__ uint32_t f2tf32(float f) {
    uint32_t u;
    asm("cvt.rna.tf32.f32 %0, %1;" : "=r"(u) : "f"(f));
    return u;
}
__device__ __forceinline__ void mma_tf32(float* c, const uint32_t* a, const uint32_t* b) {
    asm volatile(
        "mma.sync.aligned.m16n8k8.row.col.f32.tf32.tf32.f32 "
        "{%0,%1,%2,%3}, {%4,%5,%6,%7}, {%8,%9}, {%0,%1,%2,%3};"
        : "+f"(c[0]), "+f"(c[1]), "+f"(c[2]), "+f"(c[3])
        : "r"(a[0]), "r"(a[1]), "r"(a[2]), "r"(a[3]), "r"(b[0]), "r"(b[1]));
}

// ======== tf32 tensor-core NT GEMM: C[M,Nd] = A[M,Kd] @ B[Nd,Kd]^T (+bias)(+res) ========
// BM=BN=128, BK=32, 256 threads (8 warps, 2x4), warp tile 64x32 (4x4 m16n8k8 tiles).
#define SKEW 4
__global__ void __launch_bounds__(256) gemm_mma(const float* __restrict__ A,
                                                const float* __restrict__ Bw,
                                                const float* __restrict__ bias,
                                                const float* __restrict__ res,
                                                float* __restrict__ C,
                                                int Nd, int Kd) {
    __shared__ __align__(16) float As[128][32 + SKEW];
    __shared__ __align__(16) float Bs[128][32 + SKEW];

    const int t    = threadIdx.x;
    const int lane = t & 31;
    const int warp = t >> 5;
    const int wm   = (warp & 1) * 64;   // warp row offset in tile
    const int wn   = (warp >> 1) * 32;  // warp col offset in tile
    const int gid  = lane >> 2;
    const int tig  = lane & 3;

    const int m0 = blockIdx.y * 128;
    const int n0 = blockIdx.x * 128;

    // global load mapping: 2 threads per row, 16 floats each
    const int lrow = t >> 1;
    const int lcol = (t & 1) * 16;
    const float* Ap = A  + (size_t)(m0 + lrow) * Kd + lcol;
    const float* Bp = Bw + (size_t)(n0 + lrow) * Kd + lcol;

    float acc[4][4][4];
    #pragma unroll
    for (int mt = 0; mt < 4; mt++)
        #pragma unroll
        for (int nt = 0; nt < 4; nt++)
            #pragma unroll
            for (int c = 0; c < 4; c++) acc[mt][nt][c] = 0.f;

    // prefetch first k-tile into regs
    float4 pa[4], pb[4];
    #pragma unroll
    for (int j = 0; j < 4; j++) {
        pa[j] = *(const float4*)(Ap + 4 * j);
        pb[j] = *(const float4*)(Bp + 4 * j);
    }

    const int nch = Kd >> 5;
    for (int i = 0; i < nch; i++) {
        __syncthreads();   // previous compute finished with smem
        #pragma unroll
        for (int j = 0; j < 4; j++) {
            uint4 ua, ub;
            ua.x = f2tf32(pa[j].x); ua.y = f2tf32(pa[j].y);
            ua.z = f2tf32(pa[j].z); ua.w = f2tf32(pa[j].w);
            ub.x = f2tf32(pb[j].x); ub.y = f2tf32(pb[j].y);
            ub.z = f2tf32(pb[j].z); ub.w = f2tf32(pb[j].w);
            *(uint4*)&As[lrow][lcol + 4 * j] = ua;
            *(uint4*)&Bs[lrow][lcol + 4 * j] = ub;
        }
        __syncthreads();

        // prefetch next k-tile (overlaps with mma compute below)
        if (i + 1 < nch) {
            const float* An = Ap + (i + 1) * 32;
            const float* Bn = Bp + (i + 1) * 32;
            #pragma unroll
            for (int j = 0; j < 4; j++) {
                pa[j] = *(const float4*)(An + 4 * j);
                pb[j] = *(const float4*)(Bn + 4 * j);
            }
        }

        #pragma unroll
        for (int ks = 0; ks < 4; ks++) {
            const int k8 = ks * 8;
            uint32_t af[4][4], bf[4][2];
            #pragma unroll
            for (int mt = 0; mt < 4; mt++) {
                const int r = wm + mt * 16 + gid;
                af[mt][0] = __float_as_uint(As[r    ][k8 + tig]);
                af[mt][1] = __float_as_uint(As[r + 8][k8 + tig]);
                af[mt][2] = __float_as_uint(As[r    ][k8 + tig + 4]);
                af[mt][3] = __float_as_uint(As[r + 8][k8 + tig + 4]);
            }
            #pragma unroll
            for (int nt = 0; nt < 4; nt++) {
                const int cI = wn + nt * 8 + gid;
                bf[nt][0] = __float_as_uint(Bs[cI][k8 + tig]);
                bf[nt][1] = __float_as_uint(Bs[cI][k8 + tig + 4]);
            }
            #pragma unroll
            for (int mt = 0; mt < 4; mt++)
                #pragma unroll
                for (int nt = 0; nt < 4; nt++)
                    mma_tf32(acc[mt][nt], af[mt], bf[nt]);
        }
    }

    // epilogue: bias + residual, float2 stores
    #pragma unroll
    for (int mt = 0; mt < 4; mt++) {
        #pragma unroll
        for (int half = 0; half < 2; half++) {
            const int gm = m0 + wm + mt * 16 + gid + half * 8;
            float* Cp = C + (size_t)gm * Nd + n0 + wn;
            const float* Rp = res ? res + (size_t)gm * Nd + n0 + wn : nullptr;
            #pragma unroll
            for (int nt = 0; nt < 4; nt++) {
                const int cc = nt * 8 + 2 * tig;
                float v0 = acc[mt][nt][half * 2 + 0];
                float v1 = acc[mt][nt][half * 2 + 1];
                if (bias) {
                    v0 += bias[n0 + wn + cc];
                    v1 += bias[n0 + wn + cc + 1];
                }
                if (Rp) {
                    v0 += Rp[cc];
                    v1 += Rp[cc + 1];
                }
                float2 v = make_float2(v0, v1);
                *(float2*)(Cp + cc) = v;
            }
        }
    }
}

// ---------------- LayerNorm: one block per row, D=1024, 256 threads ----------------
__global__ void __launch_bounds__(256) ln_kernel(const float* __restrict__ x,
                                                 const float* __restrict__ w,
                                                 const float* __restrict__ b,
                                                 float* __restrict__ out) {
    int row = blockIdx.x;
    int t = threadIdx.x;
    const float4* xr = reinterpret_cast<const float4*>(x + (size_t)row * Dc);
    float4 v = xr[t];
    float s  = v.x + v.y + v.z + v.w;
    float ss = v.x * v.x + v.y * v.y + v.z * v.z + v.w * v.w;

    __shared__ float red0[8], red1[8];
    #pragma unroll
    for (int o = 16; o; o >>= 1) {
        s  += __shfl_xor_sync(0xffffffffu, s,  o);
        ss += __shfl_xor_sync(0xffffffffu, ss, o);
    }
    int wid = t >> 5, lid = t & 31;
    if (lid == 0) { red0[wid] = s; red1[wid] = ss; }
    __syncthreads();
    if (t == 0) {
        float a = 0.f, c = 0.f;
        #pragma unroll
        for (int i = 0; i < 8; i++) { a += red0[i]; c += red1[i]; }
        red0[0] = a; red1[0] = c;
    }
    __syncthreads();
    s = red0[0]; ss = red1[0];
    float mu   = s * (1.0f / Dc);
    float var  = ss * (1.0f / Dc) - mu * mu;
    float rstd = rsqrtf(var + 1e-5f);

    const float4* w4 = reinterpret_cast<const float4*>(w);
    const float4* b4 = reinterpret_cast<const float4*>(b);
    float4 ww = w4[t], bb = b4[t], o4;
    o4.x = (v.x - mu) * rstd * ww.x + bb.x;
    o4.y = (v.y - mu) * rstd * ww.y + bb.y;
    o4.z = (v.z - mu) * rstd * ww.z + bb.z;
    o4.w = (v.w - mu) * rstd * ww.w + bb.w;
    reinterpret_cast<float4*>(out + (size_t)row * Dc)[t] = o4;
}

// ---------------- RoPE (in-place on q,k slabs of qkv) ----------------
__global__ void rope_kernel(float* __restrict__ qkv) {
    int idx = blockIdx.x * blockDim.x + threadIdx.x;   // ROWS*H*32
    if (idx >= ROWS * Hc * (DHc / 2)) return;
    int j   = idx & 31;
    int h   = (idx >> 5) & (Hc - 1);
    int row = idx >> 9;
    int m   = row & (Mc - 1);

    float inv_freq = powf(10000.0f, -(float)(2 * j) / (float)DHc);
    float freq = (float)m * inv_freq;
    float sn, cs;
    sincosf(freq, &sn, &cs);

    float* qp = qkv + (size_t)row * QKVN + h * DHc;
    float* kp = qp + Dc;
    float q1 = qp[j], q2 = qp[32 + j];
    qp[j]      = q1 * cs - q2 * sn;
    qp[32 + j] = q1 * sn + q2 * cs;
    float k1 = kp[j], k2 = kp[32 + j];
    kp[j]      = k1 * cs - k2 * sn;
    kp[32 + j] = k1 * sn + k2 * cs;
}

// ---------------- Flash attention: 32 queries/block, 64-key tiles, online softmax ----------------
#define QT 32
#define KT 64
#define SM_QS   0
#define SM_KS   (SM_QS + QT * 65)
#define SM_VS   (SM_KS + KT * 65)
#define SM_PB   (SM_VS + KT * 64)
#define SM_M    (SM_PB + QT * 65)
#define SM_L    (SM_M + QT)
#define SM_SC   (SM_L + QT)
#define SM_MSK  (SM_SC + QT)
#define SM_FLOATS (SM_MSK + KT)
#define ATTN_SMEM_BYTES (SM_FLOATS * 4)

__global__ void __launch_bounds__(256) attn_kernel(const float* __restrict__ qkv,
                                                   const int* __restrict__ mask,
                                                   float* __restrict__ out) {
    extern __shared__ float sh[];
    float* Qs = sh + SM_QS;
    float* Ks = sh + SM_KS;
    float* Vs = sh + SM_VS;
    float* Pb = sh + SM_PB;
    float* smM = sh + SM_M;
    float* smL = sh + SM_L;
    float* smS = sh + SM_SC;
    int*   msk = reinterpret_cast<int*>(sh + SM_MSK);

    int m0 = blockIdx.x * QT;
    int h  = blockIdx.y;
    int b  = blockIdx.z;
    int t  = threadIdx.x;

    const float* qbase = qkv + (size_t)(b * Mc + m0) * QKVN + h * DHc;
    const float* kbase = qkv + (size_t)(b * Mc) * QKVN + Dc + h * DHc;
    const float* vbase = kbase + Dc;
    const int*   mbase = mask + b * Mc;

    for (int idx = t; idx < QT * DHc; idx += 256) {
        int q = idx >> 6, d = idx & 63;
        Qs[q * 65 + d] = qbase[(size_t)q * QKVN + d] * 0.125f;
    }
    if (t < QT) { smM[t] = -1e30f; smL[t] = 0.f; }

    int q  = t >> 3;
    int kg = t & 7;
    float o[8];
    #pragma unroll
    for (int j = 0; j < 8; j++) o[j] = 0.f;

    for (int n0 = 0; n0 < Mc; n0 += KT) {
        __syncthreads();
        for (int idx = t; idx < KT * DHc; idx += 256) {
            int kk = idx >> 6, d = idx & 63;
            Ks[kk * 65 + d] = kbase[(size_t)(n0 + kk) * QKVN + d];
            Vs[kk * 64 + d] = vbase[(size_t)(n0 + kk) * QKVN + d];
        }
        if (t < KT) msk[t] = mbase[n0 + t];
        __syncthreads();

        float s[8];
        #pragma unroll
        for (int i = 0; i < 8; i++) s[i] = 0.f;
        #pragma unroll
        for (int d = 0; d < DHc; d++) {
            float qv = Qs[q * 65 + d];
            #pragma unroll
            for (int i = 0; i < 8; i++) s[i] += qv * Ks[(kg + 8 * i) * 65 + d];
        }
        bool valid[8];
        float mx = -1e30f;
        #pragma unroll
        for (int i = 0; i < 8; i++) {
            valid[i] = (msk[kg + 8 * i] != 0);
            if (valid[i]) mx = fmaxf(mx, s[i]);
        }
        mx = fmaxf(mx, __shfl_xor_sync(0xffffffffu, mx, 1));
        mx = fmaxf(mx, __shfl_xor_sync(0xffffffffu, mx, 2));
        mx = fmaxf(mx, __shfl_xor_sync(0xffffffffu, mx, 4));

        float m_old = smM[q];
        float m_new = fmaxf(m_old, mx);
        float scale = __expf(m_old - m_new);
        float psum = 0.f;
        #pragma unroll
        for (int i = 0; i < 8; i++) {
            float p = valid[i] ? __expf(s[i] - m_new) : 0.f;
            Pb[q * 65 + kg + 8 * i] = p;
            psum += p;
        }
        psum += __shfl_xor_sync(0xffffffffu, psum, 1);
        psum += __shfl_xor_sync(0xffffffffu, psum, 2);
        psum += __shfl_xor_sync(0xffffffffu, psum, 4);
        if (kg == 0) {
            smL[q] = smL[q] * scale + psum;
            smM[q] = m_new;
            smS[q] = scale;
        }
        __syncthreads();

        float sc = smS[q];
        #pragma unroll
        for (int j = 0; j < 8; j++) o[j] *= sc;
        for (int kk = 0; kk < KT; kk++) {
            float p = Pb[q * 65 + kk];
            #pragma unroll
            for (int j = 0; j < 8; j++) o[j] += p * Vs[kk * 64 + kg + 8 * j];
        }
    }
    __syncthreads();
    float inv_l = 1.0f / smL[q];
    float* op = out + (size_t)(b * Mc + m0 + q) * Dc + h * DHc;
    #pragma unroll
    for (int j = 0; j < 8; j++) op[kg + 8 * j] = o[j] * inv_l;
}

// ---------------- GeGLU (exact gelu * gate) ----------------
__global__ void geglu_kernel(const float* __restrict__ g, float* __restrict__ act) {
    int idx = blockIdx.x * blockDim.x + threadIdx.x;
    if (idx >= ROWS * FFc) return;
    int r = idx / FFc;
    int j = idx - r * FFc;
    float x    = g[(size_t)r * WIN + j];
    float gate = g[(size_t)r * WIN + FFc + j];
    float ge = 0.5f * x * (1.0f + erff(x * 0.7071067811865476f));
    act[idx] = ge * gate;
}

// ---------------- launch ----------------
extern "C" void kernel_launch(void* const* d_in, const int* in_sizes, int n_in,
                              void* d_out, int out_size) {
    const float* x     = (const float*)d_in[0];
    const int*   mask  = (const int*)  d_in[1];
    const float* ln1w  = (const float*)d_in[2];
    const float* ln1b  = (const float*)d_in[3];
    const float* wqkv  = (const float*)d_in[4];
    const float* bqkv  = (const float*)d_in[5];
    const float* wo    = (const float*)d_in[6];
    const float* ln2w  = (const float*)d_in[7];
    const float* ln2b  = (const float*)d_in[8];
    const float* wi    = (const float*)d_in[9];
    const float* womlp = (const float*)d_in[10];
    float* out = (float*)d_out;

    float *xn, *qkvb, *attn, *x1, *hb, *gb, *actb;
    cudaGetSymbolAddress((void**)&xn,   g_xn);
    cudaGetSymbolAddress((void**)&qkvb, g_qkv);
    cudaGetSymbolAddress((void**)&attn, g_attn);
    cudaGetSymbolAddress((void**)&x1,   g_x1);
    cudaGetSymbolAddress((void**)&hb,   g_h);
    cudaGetSymbolAddress((void**)&gb,   g_g);
    cudaGetSymbolAddress((void**)&actb, g_act);

    cudaFuncSetAttribute(attn_kernel, cudaFuncAttributeMaxDynamicSharedMemorySize,
                         ATTN_SMEM_BYTES);

    // 1. LN1
    ln_kernel<<<ROWS, 256>>>(x, ln1w, ln1b, xn);
    // 2. QKV projection (+bias)
    gemm_mma<<<dim3(QKVN / 128, ROWS / 128), 256>>>(xn, wqkv, bqkv, nullptr, qkvb, QKVN, Dc);
    // 3. RoPE
    rope_kernel<<<(ROWS * Hc * (DHc / 2) + 255) / 256, 256>>>(qkvb);
    // 4. Attention
    attn_kernel<<<dim3(Mc / QT, Hc, Bc), 256, ATTN_SMEM_BYTES>>>(qkvb, mask, attn);
    // 5. WO projection + residual(x)
    gemm_mma<<<dim3(Dc / 128, ROWS / 128), 256>>>(attn, wo, nullptr, x, x1, Dc, Dc);
    // 6. LN2
    ln_kernel<<<ROWS, 256>>>(x1, ln2w, ln2b, hb);
    // 7. WI projection
    gemm_mma<<<dim3(WIN / 128, ROWS / 128), 256>>>(hb, wi, nullptr, nullptr, gb, WIN, Dc);
    // 8. GeGLU
    geglu_kernel<<<(ROWS * FFc + 255) / 256, 256>>>(gb, actb);
    // 9. WO_MLP projection + residual(x1) -> out
    gemm_mma<<<dim3(Dc / 128, ROWS / 128), 256>>>(actb, womlp, nullptr, x1, out, Dc, FFc);
}